// round 1
// baseline (speedup 1.0000x reference)
#include <cuda_runtime.h>
#include <math.h>

#define NUM_CLASS 20
#define IGNORE 255
#define DD 256
#define HH 256
#define WW 32
#define SPATIAL (DD*HH*WW)   // 2,097,152

__device__ double g_num;
__device__ double g_den;

__global__ void zero_acc_kernel() {
    g_num = 0.0;
    g_den = 0.0;
}

__device__ __forceinline__ float gval(int a, int b) {
    // sum_c |onehot(a) - onehot(b)| with onehot(IGNORE)=0
    if (a == b) return 0.0f;
    if (a == IGNORE || b == IGNORE) return 1.0f;
    return 2.0f;
}

__global__ void __launch_bounds__(256)
loss_kernel(const float* __restrict__ pred,
            const int*   __restrict__ tgt,
            const float* __restrict__ cw) {
    const int s = blockIdx.x * blockDim.x + threadIdx.x;

    float num = 0.0f;
    float den = 0.0f;

    if (s < SPATIAL) {
        const int t = __ldg(&tgt[s]);
        const bool valid = (t != IGNORE);
        const int tc = valid ? t : 0;

        // ---- log_softmax at class t: single pass over 20 channels ----
        float v[NUM_CLASS];
        #pragma unroll
        for (int c = 0; c < NUM_CLASS; c++) {
            v[c] = __ldg(&pred[c * SPATIAL + s]);
        }
        float m = v[0];
        #pragma unroll
        for (int c = 1; c < NUM_CLASS; c++) m = fmaxf(m, v[c]);
        float sum = 0.0f;
        #pragma unroll
        for (int c = 0; c < NUM_CLASS; c++) sum += expf(v[c] - m);
        const float logp_t = v[tc] - m - logf(sum);

        const float w = __ldg(&cw[tc]);
        const float loss = valid ? (-w * logp_t) : 0.0f;
        den = valid ? w : 0.0f;

        // ---- LGA weight: pure label-neighbor function ----
        const int wq = s & (WW - 1);
        const int h  = (s >> 5) & (HH - 1);
        const int d  = s >> 13;   // s / (WW*HH)

        float lga = 0.0f;

        // W axis (stride 1)
        {
            int a, b; float sc;
            if (wq == 0)            { a = t;                    b = __ldg(&tgt[s + 1]);  sc = 1.0f; }
            else if (wq == WW - 1)  { a = __ldg(&tgt[s - 1]);   b = t;                   sc = 1.0f; }
            else                    { a = __ldg(&tgt[s - 1]);   b = __ldg(&tgt[s + 1]);  sc = 0.5f; }
            lga += sc * gval(a, b);
        }
        // H axis (stride WW)
        {
            int a, b; float sc;
            if (h == 0)             { a = t;                     b = __ldg(&tgt[s + WW]); sc = 1.0f; }
            else if (h == HH - 1)   { a = __ldg(&tgt[s - WW]);   b = t;                   sc = 1.0f; }
            else                    { a = __ldg(&tgt[s - WW]);   b = __ldg(&tgt[s + WW]); sc = 0.5f; }
            lga += sc * gval(a, b);
        }
        // D axis (stride WW*HH)
        {
            const int sd = WW * HH;
            int a, b; float sc;
            if (d == 0)             { a = t;                     b = __ldg(&tgt[s + sd]); sc = 1.0f; }
            else if (d == DD - 1)   { a = __ldg(&tgt[s - sd]);   b = t;                   sc = 1.0f; }
            else                    { a = __ldg(&tgt[s - sd]);   b = __ldg(&tgt[s + sd]); sc = 0.5f; }
            lga += sc * gval(a, b);
        }

        const float lga_w = 1.0f + lga;   // ALPHA=1, BETA=1
        num = loss * lga_w;
    }

    // ---- block reduction (float within warp/block, double across blocks) ----
    #pragma unroll
    for (int off = 16; off > 0; off >>= 1) {
        num += __shfl_down_sync(0xFFFFFFFFu, num, off);
        den += __shfl_down_sync(0xFFFFFFFFu, den, off);
    }

    __shared__ float s_num[8];
    __shared__ float s_den[8];
    const int lane = threadIdx.x & 31;
    const int wid  = threadIdx.x >> 5;
    if (lane == 0) { s_num[wid] = num; s_den[wid] = den; }
    __syncthreads();

    if (wid == 0) {
        num = (lane < 8) ? s_num[lane] : 0.0f;
        den = (lane < 8) ? s_den[lane] : 0.0f;
        #pragma unroll
        for (int off = 4; off > 0; off >>= 1) {
            num += __shfl_down_sync(0xFFFFFFFFu, num, off);
            den += __shfl_down_sync(0xFFFFFFFFu, den, off);
        }
        if (lane == 0) {
            atomicAdd(&g_num, (double)num);
            atomicAdd(&g_den, (double)den);
        }
    }
}

__global__ void finalize_kernel(float* __restrict__ out) {
    out[0] = (float)(g_num / g_den);
}

extern "C" void kernel_launch(void* const* d_in, const int* in_sizes, int n_in,
                              void* d_out, int out_size) {
    const float* pred = (const float*)d_in[0];
    const int*   tgt  = (const int*)d_in[1];
    const float* cw   = (const float*)d_in[2];
    float* out = (float*)d_out;

    zero_acc_kernel<<<1, 1>>>();
    const int threads = 256;
    const int blocks = (SPATIAL + threads - 1) / threads;  // 8192
    loss_kernel<<<blocks, threads>>>(pred, tgt, cw);
    finalize_kernel<<<1, 1>>>(out);
}